// round 4
// baseline (speedup 1.0000x reference)
#include <cuda_runtime.h>
#include <math.h>

// dims
#define B_ 4096
#define D_ 256
#define H_ 1024
#define K_ 128
#define ND (B_*D_)
#define NV (ND/4)          // float4 count
#define NMAX 20            // max attempted dopri5 steps (device-side early exit)
#define RTOL 1e-3f
#define ATOL 1e-3f

// dopri5 error coefficients (c_sol - c_bhat)
#define CE0 ((float)(35.0/384.0 - 1951.0/21600.0))
#define CE2 ((float)(500.0/1113.0 - 22642.0/50085.0))
#define CE3 ((float)(125.0/192.0 - 451.0/720.0))
#define CE4 ((float)(-2187.0/6784.0 + 12231.0/42400.0))
#define CE5 ((float)(11.0/84.0 - 649.0/6300.0))
#define CE6 ((float)(-1.0/60.0))
// dopri5 midpoint coefficients (interp fit)
#define CM0 ((float)(6025192743.0/30085553152.0/2.0))
#define CM2 ((float)(51252292925.0/65400821598.0/2.0))
#define CM3 ((float)(-2691868925.0/45128329728.0/2.0))
#define CM4 ((float)(187940372067.0/1594534317056.0/2.0))
#define CM5 ((float)(-1776094331.0/19743644256.0/2.0))
#define CM6 ((float)(11237099.0/235043384.0/2.0))

struct Ctl {
    float t, dt, last_t, dt_used, h0, d1;
    int accept, done;
};
__device__ Ctl g_ctl;
__device__ float g_y[ND];
__device__ float g_y1[ND];
__device__ float g_k[7][ND];
__device__ float g_h1[B_ * H_];
__device__ float g_y0s[ND], g_ymid[ND], g_f0s[ND], g_f1s[ND];
__device__ float g_yout[ND];
__device__ float g_part[2048];

__global__ void ctl_init_kernel() {
    if (threadIdx.x == 0 && blockIdx.x == 0) {
        g_ctl.t = 0.f; g_ctl.dt = 0.f; g_ctl.last_t = 0.f; g_ctl.dt_used = 0.f;
        g_ctl.h0 = 0.f; g_ctl.d1 = 0.f; g_ctl.accept = 0; g_ctl.done = 0;
    }
}

__global__ void copy_kernel(const float4* __restrict__ src, float4* __restrict__ dst) {
    int i = blockIdx.x * 256 + threadIdx.x;
    dst[i] = src[i];
}

// ---------------- GEMM tiling ----------------
#define BM 128
#define BN 64
#define BKT 16
#define TM 8
#define TN 4

// GEMM A (layer 1, combine fused): h1 = tanh((Y + dt*sum cj k_j) @ W1 + b1)
// M=4096, N=1024, K=256. Optionally writes the combined input (stage-6 y1).
__global__ __launch_bounds__(256) void gemm_a_kernel(
    const float* __restrict__ Y, const float* __restrict__ W,
    const float* __restrict__ bias, float* __restrict__ C,
    const float* __restrict__ scal, int nk,
    float c0, float c1, float c2, float c3, float c4, float c5,
    float* __restrict__ Xout)
{
    if (g_ctl.done) return;
    const int Nn = H_, Kd = D_;
    __shared__ float As[BKT][BM + 4];
    __shared__ float Bs[BKT][BN];

    const int tid = threadIdx.x;
    const int tx = tid & 15;
    const int ty = tid >> 4;
    const int m0 = blockIdx.y * BM;
    const int n0 = blockIdx.x * BN;
    const float dt = *scal;
    float cc[6] = {c0, c1, c2, c3, c4, c5};

    float acc[TM][TN];
#pragma unroll
    for (int i = 0; i < TM; i++)
#pragma unroll
        for (int j = 0; j < TN; j++) acc[i][j] = 0.0f;

    for (int k0 = 0; k0 < Kd; k0 += BKT) {
#pragma unroll
        for (int i = 0; i < 2; i++) {
            int t = tid + i * 256;
            int row = t >> 2;
            int kv  = (t & 3) * 4;
            size_t off = (size_t)(m0 + row) * Kd + k0 + kv;
            float4 v = *(const float4*)&Y[off];
            float4 s = make_float4(0.f, 0.f, 0.f, 0.f);
            for (int j = 0; j < nk; j++) {
                const float4 kj = *(const float4*)&g_k[j][off];
                s.x += cc[j] * kj.x; s.y += cc[j] * kj.y;
                s.z += cc[j] * kj.z; s.w += cc[j] * kj.w;
            }
            v.x += dt * s.x; v.y += dt * s.y; v.z += dt * s.z; v.w += dt * s.w;
            if (Xout && blockIdx.x == 0) *(float4*)&Xout[off] = v;
            As[kv + 0][row] = v.x;
            As[kv + 1][row] = v.y;
            As[kv + 2][row] = v.z;
            As[kv + 3][row] = v.w;
        }
        {
            int row = tid >> 4;
            int nv  = (tid & 15) * 4;
            *(float4*)&Bs[row][nv] = *(const float4*)&W[(size_t)(k0 + row) * Nn + n0 + nv];
        }
        __syncthreads();

#pragma unroll
        for (int kk = 0; kk < BKT; kk++) {
            float a[TM], b[TN];
#pragma unroll
            for (int i = 0; i < TM; i++) a[i] = As[kk][ty * TM + i];
#pragma unroll
            for (int j = 0; j < TN; j++) b[j] = Bs[kk][tx * TN + j];
#pragma unroll
            for (int i = 0; i < TM; i++)
#pragma unroll
                for (int j = 0; j < TN; j++)
                    acc[i][j] += a[i] * b[j];
        }
        __syncthreads();
    }

#pragma unroll
    for (int i = 0; i < TM; i++) {
        int m = m0 + ty * TM + i;
#pragma unroll
        for (int j = 0; j < TN; j++) {
            int n = n0 + tx * TN + j;
            C[(size_t)m * Nn + n] = tanhf(acc[i][j] + bias[n]);
        }
    }
}

// GEMM B (layer 2): kout = h1 @ W2 + b2. M=4096, N=256, K=1024.
// do_err: also accumulate dopri5 error-ratio partials (kout == k6 case).
__global__ __launch_bounds__(256) void gemm_b_kernel(
    const float* __restrict__ A, const float* __restrict__ W,
    const float* __restrict__ bias, float* __restrict__ C, int do_err)
{
    if (g_ctl.done) return;
    const int Nn = D_, Kd = H_;
    __shared__ float As[BKT][BM + 4];
    __shared__ float Bs[BKT][BN];

    const int tid = threadIdx.x;
    const int tx = tid & 15;
    const int ty = tid >> 4;
    const int m0 = blockIdx.y * BM;
    const int n0 = blockIdx.x * BN;

    float acc[TM][TN];
#pragma unroll
    for (int i = 0; i < TM; i++)
#pragma unroll
        for (int j = 0; j < TN; j++) acc[i][j] = 0.0f;

    for (int k0 = 0; k0 < Kd; k0 += BKT) {
#pragma unroll
        for (int i = 0; i < 2; i++) {
            int t = tid + i * 256;
            int row = t >> 2;
            int kv  = (t & 3) * 4;
            const float4 a4 = *(const float4*)&A[(size_t)(m0 + row) * Kd + k0 + kv];
            As[kv + 0][row] = a4.x;
            As[kv + 1][row] = a4.y;
            As[kv + 2][row] = a4.z;
            As[kv + 3][row] = a4.w;
        }
        {
            int row = tid >> 4;
            int nv  = (tid & 15) * 4;
            *(float4*)&Bs[row][nv] = *(const float4*)&W[(size_t)(k0 + row) * Nn + n0 + nv];
        }
        __syncthreads();

#pragma unroll
        for (int kk = 0; kk < BKT; kk++) {
            float a[TM], b[TN];
#pragma unroll
            for (int i = 0; i < TM; i++) a[i] = As[kk][ty * TM + i];
#pragma unroll
            for (int j = 0; j < TN; j++) b[j] = Bs[kk][tx * TN + j];
#pragma unroll
            for (int i = 0; i < TM; i++)
#pragma unroll
                for (int j = 0; j < TN; j++)
                    acc[i][j] += a[i] * b[j];
        }
        __syncthreads();
    }

    float bj[TN];
#pragma unroll
    for (int j = 0; j < TN; j++) bj[j] = bias[n0 + tx * TN + j];

    float vout[TM][TN];
#pragma unroll
    for (int i = 0; i < TM; i++) {
        int m = m0 + ty * TM + i;
#pragma unroll
        for (int j = 0; j < TN; j++) {
            vout[i][j] = acc[i][j] + bj[j];
            C[(size_t)m * Nn + n0 + tx * TN + j] = vout[i][j];
        }
    }

    if (do_err) {
        const float dt = g_ctl.dt;
        float s = 0.f;
#pragma unroll
        for (int i = 0; i < TM; i++) {
            size_t off = (size_t)(m0 + ty * TM + i) * D_ + n0 + tx * TN;
            float4 y4  = *(const float4*)&g_y[off];
            float4 y14 = *(const float4*)&g_y1[off];
            float4 k0v = *(const float4*)&g_k[0][off];
            float4 k2v = *(const float4*)&g_k[2][off];
            float4 k3v = *(const float4*)&g_k[3][off];
            float4 k4v = *(const float4*)&g_k[4][off];
            float4 k5v = *(const float4*)&g_k[5][off];
#define ERRC(c, jj) { \
            float e = dt * (CE0*k0v.c + CE2*k2v.c + CE3*k3v.c + CE4*k4v.c + CE5*k5v.c + CE6*vout[i][jj]); \
            float tol = ATOL + RTOL * fmaxf(fabsf(y4.c), fabsf(y14.c)); \
            float r = e / tol; s += r * r; }
            ERRC(x, 0) ERRC(y, 1) ERRC(z, 2) ERRC(w, 3)
#undef ERRC
        }
        __shared__ float sm[256];
        sm[tid] = s;
        __syncthreads();
        for (int off = 128; off > 0; off >>= 1) {
            if (tid < off) sm[tid] += sm[tid + off];
            __syncthreads();
        }
        if (tid == 0) g_part[blockIdx.y * gridDim.x + blockIdx.x] = sm[0];
    }
}

// ---------------- init-step-size reductions ----------------
__global__ void red_d01_kernel() {
    int i = blockIdx.x * 256 + threadIdx.x;
    float4 yv = ((const float4*)g_y)[i];
    float4 fv = ((const float4*)g_k[0])[i];
    float s0 = 0.f, s1 = 0.f;
    {
        float sc, a, b;
        sc = ATOL + fabsf(yv.x) * RTOL; a = yv.x / sc; b = fv.x / sc; s0 += a*a; s1 += b*b;
        sc = ATOL + fabsf(yv.y) * RTOL; a = yv.y / sc; b = fv.y / sc; s0 += a*a; s1 += b*b;
        sc = ATOL + fabsf(yv.z) * RTOL; a = yv.z / sc; b = fv.z / sc; s0 += a*a; s1 += b*b;
        sc = ATOL + fabsf(yv.w) * RTOL; a = yv.w / sc; b = fv.w / sc; s0 += a*a; s1 += b*b;
    }
    __shared__ float sm0[256], sm1[256];
    sm0[threadIdx.x] = s0; sm1[threadIdx.x] = s1;
    __syncthreads();
    for (int off = 128; off > 0; off >>= 1) {
        if (threadIdx.x < off) {
            sm0[threadIdx.x] += sm0[threadIdx.x + off];
            sm1[threadIdx.x] += sm1[threadIdx.x + off];
        }
        __syncthreads();
    }
    if (threadIdx.x == 0) { g_part[blockIdx.x] = sm0[0]; g_part[1024 + blockIdx.x] = sm1[0]; }
}

__global__ void fin_d01_kernel() {
    __shared__ float sm0[256], sm1[256];
    float s0 = 0.f, s1 = 0.f;
    for (int j = threadIdx.x; j < 1024; j += 256) { s0 += g_part[j]; s1 += g_part[1024 + j]; }
    sm0[threadIdx.x] = s0; sm1[threadIdx.x] = s1;
    __syncthreads();
    for (int off = 128; off > 0; off >>= 1) {
        if (threadIdx.x < off) {
            sm0[threadIdx.x] += sm0[threadIdx.x + off];
            sm1[threadIdx.x] += sm1[threadIdx.x + off];
        }
        __syncthreads();
    }
    if (threadIdx.x == 0) {
        float d0 = sqrtf(sm0[0]);
        float d1 = sqrtf(sm1[0]);
        float h0 = (d0 < 1e-5f || d1 < 1e-5f) ? 1e-6f : 0.01f * d0 / d1;
        g_ctl.h0 = h0;
        g_ctl.d1 = d1;
    }
}

__global__ void red_d2_kernel() {
    int i = blockIdx.x * 256 + threadIdx.x;
    float4 yv = ((const float4*)g_y)[i];
    float4 f0 = ((const float4*)g_k[0])[i];
    float4 f1 = ((const float4*)g_k[1])[i];
    float s = 0.f;
    {
        float sc, a;
        sc = ATOL + fabsf(yv.x) * RTOL; a = (f1.x - f0.x) / sc; s += a*a;
        sc = ATOL + fabsf(yv.y) * RTOL; a = (f1.y - f0.y) / sc; s += a*a;
        sc = ATOL + fabsf(yv.z) * RTOL; a = (f1.z - f0.z) / sc; s += a*a;
        sc = ATOL + fabsf(yv.w) * RTOL; a = (f1.w - f0.w) / sc; s += a*a;
    }
    __shared__ float sm[256];
    sm[threadIdx.x] = s;
    __syncthreads();
    for (int off = 128; off > 0; off >>= 1) {
        if (threadIdx.x < off) sm[threadIdx.x] += sm[threadIdx.x + off];
        __syncthreads();
    }
    if (threadIdx.x == 0) g_part[blockIdx.x] = sm[0];
}

__global__ void fin_d2_kernel() {
    __shared__ float sm[256];
    float s = 0.f;
    for (int j = threadIdx.x; j < 1024; j += 256) s += g_part[j];
    sm[threadIdx.x] = s;
    __syncthreads();
    for (int off = 128; off > 0; off >>= 1) {
        if (threadIdx.x < off) sm[threadIdx.x] += sm[threadIdx.x + off];
        __syncthreads();
    }
    if (threadIdx.x == 0) {
        float d2 = sqrtf(sm[0]) / g_ctl.h0;
        float d1 = g_ctl.d1;
        float h1;
        if (d1 <= 1e-15f && d2 <= 1e-15f)
            h1 = fmaxf(1e-6f, g_ctl.h0 * 1e-3f);
        else
            h1 = powf(0.01f / fmaxf(d1, d2), 0.2f);
        float dt = fminf(100.f * g_ctl.h0, h1);
        g_ctl.dt = dt;
        g_ctl.t = 0.f; g_ctl.last_t = 0.f;
        g_ctl.done = 0; g_ctl.accept = 0;
    }
}

// ---------------- controller (sums 128 partials from gemm_b stage 6) ----------------
__global__ void ctl_step_kernel() {
    if (g_ctl.done) { if (threadIdx.x == 0) g_ctl.accept = 0; return; }
    __shared__ float sm[128];
    sm[threadIdx.x] = g_part[threadIdx.x];
    __syncthreads();
    for (int off = 64; off > 0; off >>= 1) {
        if (threadIdx.x < off) sm[threadIdx.x] += sm[threadIdx.x + off];
        __syncthreads();
    }
    if (threadIdx.x == 0) {
        float ratio = sqrtf(sm[0] / (float)ND);
        float t = g_ctl.t, dt = g_ctl.dt;
        float next_t = t + dt;
        int acc = (ratio <= 1.0f);
        float fac;
        if (ratio == 0.f) {
            fac = 10.f;
        } else {
            float r = fmaxf(ratio, 0.f);
            float dfac = (r < 1.f) ? 1.f : 0.2f;
            fac = fminf(10.f, fmaxf(0.9f * powf(r, -0.2f), dfac));
        }
        float ndt = fmaxf(dt * fac, 0.f);
        g_ctl.dt_used = dt;
        g_ctl.dt = ndt;
        g_ctl.accept = acc;
        if (acc) {
            g_ctl.last_t = t;
            g_ctl.t = next_t;
            if (next_t >= 1.0f) g_ctl.done = 1;
        }
    }
}

// ---------------- accept: snapshot, commit, FSAL ----------------
__global__ void apply_kernel() {
    if (!g_ctl.accept) return;
    int i = blockIdx.x * 256 + threadIdx.x;
    float dts = g_ctl.dt_used;
    float4 yv = ((const float4*)g_y)[i];
    float4 y1 = ((const float4*)g_y1)[i];
    float4 k0 = ((const float4*)g_k[0])[i];
    float4 k2 = ((const float4*)g_k[2])[i];
    float4 k3 = ((const float4*)g_k[3])[i];
    float4 k4 = ((const float4*)g_k[4])[i];
    float4 k5 = ((const float4*)g_k[5])[i];
    float4 k6 = ((const float4*)g_k[6])[i];
    float4 ym;
    ym.x = yv.x + dts * (CM0*k0.x + CM2*k2.x + CM3*k3.x + CM4*k4.x + CM5*k5.x + CM6*k6.x);
    ym.y = yv.y + dts * (CM0*k0.y + CM2*k2.y + CM3*k3.y + CM4*k4.y + CM5*k5.y + CM6*k6.y);
    ym.z = yv.z + dts * (CM0*k0.z + CM2*k2.z + CM3*k3.z + CM4*k4.z + CM5*k5.z + CM6*k6.z);
    ym.w = yv.w + dts * (CM0*k0.w + CM2*k2.w + CM3*k3.w + CM4*k4.w + CM5*k5.w + CM6*k6.w);
    ((float4*)g_y0s)[i] = yv;
    ((float4*)g_f0s)[i] = k0;
    ((float4*)g_f1s)[i] = k6;
    ((float4*)g_ymid)[i] = ym;
    ((float4*)g_y)[i] = y1;       // commit
    ((float4*)g_k[0])[i] = k6;    // FSAL
}

// ---------------- final quartic interpolation at t=1 ----------------
__global__ void interp_kernel() {
    int i = blockIdx.x * 256 + threadIdx.x;
    float t1 = g_ctl.t, t0 = g_ctl.last_t, dts = g_ctl.dt_used;
    float x = (1.0f - t0) / (t1 - t0);
    float4 y0 = ((const float4*)g_y0s)[i];
    float4 y1 = ((const float4*)g_y)[i];
    float4 f0 = ((const float4*)g_f0s)[i];
    float4 f1 = ((const float4*)g_f1s)[i];
    float4 ym = ((const float4*)g_ymid)[i];
    float4 o;
#define INTERPC(c) { \
        float a = 2.f*dts*(f1.c - f0.c) - 8.f*(y1.c + y0.c) + 16.f*ym.c; \
        float b = dts*(5.f*f0.c - 3.f*f1.c) + 18.f*y0.c + 14.f*y1.c - 32.f*ym.c; \
        float cc = dts*(f1.c - 4.f*f0.c) - 11.f*y0.c - 5.f*y1.c + 16.f*ym.c; \
        float d = dts*f0.c; \
        float e = y0.c; \
        o.c = (((a*x + b)*x + cc)*x + d)*x + e; }
    INTERPC(x) INTERPC(y) INTERPC(z) INTERPC(w)
#undef INTERPC
    ((float4*)g_yout)[i] = o;
}

__global__ void gather_kernel(const int* __restrict__ indices, float* __restrict__ out) {
    int i = blockIdx.x * 256 + threadIdx.x;
    if (i < B_ * K_) {
        int b = i / K_;
        out[i] = g_yout[(size_t)b * D_ + indices[i]];
    }
}

// ---------------- orchestration ----------------
extern "C" void kernel_launch(void* const* d_in, const int* in_sizes, int n_in,
                              void* d_out, int out_size)
{
    const float* x  = (const float*)d_in[0];
    const float* W1 = (const float*)d_in[1];
    const float* b1 = (const float*)d_in[2];
    const float* W2 = (const float*)d_in[3];
    const float* b2 = (const float*)d_in[4];
    const int*  idx = (const int*)d_in[5];
    float* out = (float*)d_out;

    float *y, *y1, *h1, *k[7];
    Ctl* ctl;
    cudaGetSymbolAddress((void**)&y,   g_y);
    cudaGetSymbolAddress((void**)&y1,  g_y1);
    cudaGetSymbolAddress((void**)&h1,  g_h1);
    cudaGetSymbolAddress((void**)&ctl, g_ctl);
    {
        float* kbase;
        cudaGetSymbolAddress((void**)&kbase, g_k);
        for (int j = 0; j < 7; j++) k[j] = kbase + (size_t)j * ND;
    }
    const float* dt_ptr = &ctl->dt;
    const float* h0_ptr = &ctl->h0;

    dim3 g1(H_ / BN, B_ / BM), g2(D_ / BN, B_ / BM), blk(256);
    dim3 ge(NV / 256), be(256);

    // dopri5 Butcher tableau
    const float B21 = (float)(1.0/5.0);
    const float B31 = (float)(3.0/40.0),   B32 = (float)(9.0/40.0);
    const float B41 = (float)(44.0/45.0),  B42 = (float)(-56.0/15.0),  B43 = (float)(32.0/9.0);
    const float B51 = (float)(19372.0/6561.0), B52 = (float)(-25360.0/2187.0),
                B53 = (float)(64448.0/6561.0), B54 = (float)(-212.0/729.0);
    const float B61 = (float)(9017.0/3168.0),  B62 = (float)(-355.0/33.0),
                B63 = (float)(46732.0/5247.0), B64 = (float)(49.0/176.0),
                B65 = (float)(-5103.0/18656.0);
    const float CS0 = (float)(35.0/384.0), CS2 = (float)(500.0/1113.0),
                CS3 = (float)(125.0/192.0), CS4 = (float)(-2187.0/6784.0),
                CS5 = (float)(11.0/84.0);

    // init: ctl, y=x, k0=f(y)
    ctl_init_kernel<<<1, 32>>>();
    copy_kernel<<<ge, be>>>((const float4*)x, (float4*)y);
    gemm_a_kernel<<<g1, blk>>>(y, W1, b1, h1, h0_ptr, 0,
                               0.f, 0.f, 0.f, 0.f, 0.f, 0.f, nullptr);
    gemm_b_kernel<<<g2, blk>>>(h1, W2, b2, k[0], 0);
    // initial step size (Hairer)
    red_d01_kernel<<<ge, be>>>();
    fin_d01_kernel<<<1, 256>>>();
    gemm_a_kernel<<<g1, blk>>>(y, W1, b1, h1, h0_ptr, 1,
                               1.f, 0.f, 0.f, 0.f, 0.f, 0.f, nullptr);
    gemm_b_kernel<<<g2, blk>>>(h1, W2, b2, k[1], 0);
    red_d2_kernel<<<ge, be>>>();
    fin_d2_kernel<<<1, 256>>>();

    for (int s = 0; s < NMAX; s++) {
        // stage 1
        gemm_a_kernel<<<g1, blk>>>(y, W1, b1, h1, dt_ptr, 1,
                                   B21, 0.f, 0.f, 0.f, 0.f, 0.f, nullptr);
        gemm_b_kernel<<<g2, blk>>>(h1, W2, b2, k[1], 0);
        // stage 2
        gemm_a_kernel<<<g1, blk>>>(y, W1, b1, h1, dt_ptr, 2,
                                   B31, B32, 0.f, 0.f, 0.f, 0.f, nullptr);
        gemm_b_kernel<<<g2, blk>>>(h1, W2, b2, k[2], 0);
        // stage 3
        gemm_a_kernel<<<g1, blk>>>(y, W1, b1, h1, dt_ptr, 3,
                                   B41, B42, B43, 0.f, 0.f, 0.f, nullptr);
        gemm_b_kernel<<<g2, blk>>>(h1, W2, b2, k[3], 0);
        // stage 4
        gemm_a_kernel<<<g1, blk>>>(y, W1, b1, h1, dt_ptr, 4,
                                   B51, B52, B53, B54, 0.f, 0.f, nullptr);
        gemm_b_kernel<<<g2, blk>>>(h1, W2, b2, k[4], 0);
        // stage 5
        gemm_a_kernel<<<g1, blk>>>(y, W1, b1, h1, dt_ptr, 5,
                                   B61, B62, B63, B64, B65, 0.f, nullptr);
        gemm_b_kernel<<<g2, blk>>>(h1, W2, b2, k[5], 0);
        // stage 6: input y1 = y + dt*dot(c_sol, k) (written to g_y1), k6 = f(y1), err partials
        gemm_a_kernel<<<g1, blk>>>(y, W1, b1, h1, dt_ptr, 6,
                                   CS0, 0.f, CS2, CS3, CS4, CS5, y1);
        gemm_b_kernel<<<g2, blk>>>(h1, W2, b2, k[6], 1);
        // controller + conditional commit
        ctl_step_kernel<<<1, 128>>>();
        apply_kernel<<<ge, be>>>();
    }

    // interpolate to t=1 and gather
    interp_kernel<<<ge, be>>>();
    {
        int n = B_ * K_;
        gather_kernel<<<(n + 255) / 256, 256>>>(idx, out);
    }
}

// round 6
// speedup vs baseline: 2.3694x; 2.3694x over previous
#include <cuda_runtime.h>
#include <cuda_bf16.h>
#include <cstdint>
#include <math.h>

// dims
#define B_ 4096
#define D_ 256
#define H_ 1024
#define K_ 128
#define ND (B_*D_)
#define NV (ND/4)
#define NMAX 10
#define RTOL 1e-3f
#define ATOL 1e-3f

// dopri5 error coefficients (c_sol - c_bhat)
#define CE0 ((float)(35.0/384.0 - 1951.0/21600.0))
#define CE2 ((float)(500.0/1113.0 - 22642.0/50085.0))
#define CE3 ((float)(125.0/192.0 - 451.0/720.0))
#define CE4 ((float)(-2187.0/6784.0 + 12231.0/42400.0))
#define CE5 ((float)(11.0/84.0 - 649.0/6300.0))
#define CE6 ((float)(-1.0/60.0))
// dopri5 midpoint coefficients (interp fit)
#define CM0 ((float)(6025192743.0/30085553152.0/2.0))
#define CM2 ((float)(51252292925.0/65400821598.0/2.0))
#define CM3 ((float)(-2691868925.0/45128329728.0/2.0))
#define CM4 ((float)(187940372067.0/1594534317056.0/2.0))
#define CM5 ((float)(-1776094331.0/19743644256.0/2.0))
#define CM6 ((float)(11237099.0/235043384.0/2.0))

struct Ctl {
    float t, dt, last_t, dt_used, h0, d1;
    int accept, done;
};
__device__ Ctl g_ctl;
__device__ __align__(16) float g_y[ND];
__device__ __align__(16) float g_y1[ND];
__device__ __align__(16) float g_k[7][ND];
__device__ __align__(16) float g_y0s[ND], g_ymid[ND], g_f0s[ND], g_f1s[ND];
__device__ __align__(16) float g_yout[ND];
__device__ __align__(16) float g_part[2048];
__device__ __align__(16) float g_p2[2 * ND];                    // split-K partials
__device__ __align__(16) __nv_bfloat16 g_Xhi[ND], g_Xlo[ND];
__device__ __align__(16) __nv_bfloat16 g_Hhi[B_ * H_], g_Hlo[B_ * H_];
__device__ __align__(16) __nv_bfloat16 g_W1thi[H_ * D_], g_W1tlo[H_ * D_]; // W1^T [H,D]
__device__ __align__(16) __nv_bfloat16 g_W2thi[D_ * H_], g_W2tlo[D_ * H_]; // W2^T [D,H]

#define SWZ128(b) ((b) ^ (((b) >> 3) & 0x70))

__device__ __forceinline__ uint32_t smem_u32(const void* p) {
    uint32_t a;
    asm("{ .reg .u64 t; cvta.to.shared.u64 t, %1; cvt.u32.u64 %0, t; }" : "=r"(a) : "l"(p));
    return a;
}
__device__ __forceinline__ void ldsm_x4(uint32_t* r, uint32_t addr) {
    asm volatile("ldmatrix.sync.aligned.m8n8.x4.shared.b16 {%0,%1,%2,%3}, [%4];"
        : "=r"(r[0]), "=r"(r[1]), "=r"(r[2]), "=r"(r[3]) : "r"(addr));
}
__device__ __forceinline__ void ldsm_x2(uint32_t* r, uint32_t addr) {
    asm volatile("ldmatrix.sync.aligned.m8n8.x2.shared.b16 {%0,%1}, [%2];"
        : "=r"(r[0]), "=r"(r[1]) : "r"(addr));
}
__device__ __forceinline__ void mma16816(float* c, const uint32_t* a, const uint32_t* b) {
    asm volatile("mma.sync.aligned.m16n8k16.row.col.f32.bf16.bf16.f32 "
        "{%0,%1,%2,%3}, {%4,%5,%6,%7}, {%8,%9}, {%0,%1,%2,%3};"
        : "+f"(c[0]), "+f"(c[1]), "+f"(c[2]), "+f"(c[3])
        : "r"(a[0]), "r"(a[1]), "r"(a[2]), "r"(a[3]), "r"(b[0]), "r"(b[1]));
}

// ================= small kernels =================
__global__ void ctl_init_kernel() {
    if (threadIdx.x == 0 && blockIdx.x == 0) {
        g_ctl.t = 0.f; g_ctl.dt = 0.f; g_ctl.last_t = 0.f; g_ctl.dt_used = 0.f;
        g_ctl.h0 = 0.f; g_ctl.d1 = 0.f; g_ctl.accept = 0; g_ctl.done = 0;
    }
}

__global__ void copy_kernel(const float4* __restrict__ src, float4* __restrict__ dst) {
    int i = blockIdx.x * 256 + threadIdx.x;
    dst[i] = src[i];
}

// weight prep: W1 [D,H] -> W1t hi/lo [H,D]
__global__ void prep_w1_kernel(const float* __restrict__ W1) {
    int o = blockIdx.x * 256 + threadIdx.x;
    if (o < H_ * D_) {
        int h = o >> 8, d = o & 255;
        float v = W1[(size_t)d * H_ + h];
        __nv_bfloat16 hi = __float2bfloat16(v);
        g_W1thi[o] = hi;
        g_W1tlo[o] = __float2bfloat16(v - __bfloat162float(hi));
    }
}
// W2 [H,D] -> W2t hi/lo [D,H]
__global__ void prep_w2_kernel(const float* __restrict__ W2) {
    int o = blockIdx.x * 256 + threadIdx.x;
    if (o < D_ * H_) {
        int d = o >> 10, h = o & 1023;
        float v = W2[(size_t)h * D_ + d];
        __nv_bfloat16 hi = __float2bfloat16(v);
        g_W2thi[o] = hi;
        g_W2tlo[o] = __float2bfloat16(v - __bfloat162float(hi));
    }
}

// stage combine + bf16 split: X = y + dt*sum cj k_j -> Xhi, Xlo [, y1]
__global__ void split_combine_kernel(const float4* __restrict__ y,
                                     const float* __restrict__ scal, int nk,
                                     float c0, float c1, float c2, float c3, float c4, float c5,
                                     int write_y1)
{
    if (g_ctl.done) return;
    int i = blockIdx.x * 256 + threadIdx.x;
    float dt = *scal;
    float cc[6] = {c0, c1, c2, c3, c4, c5};
    float4 s = make_float4(0.f, 0.f, 0.f, 0.f);
    for (int j = 0; j < nk; j++) {
        float4 kv = ((const float4*)g_k[j])[i];
        s.x += cc[j] * kv.x; s.y += cc[j] * kv.y;
        s.z += cc[j] * kv.z; s.w += cc[j] * kv.w;
    }
    float4 yv = y[i];
    float4 X = make_float4(yv.x + dt * s.x, yv.y + dt * s.y,
                           yv.z + dt * s.z, yv.w + dt * s.w);
    if (write_y1) ((float4*)g_y1)[i] = X;
    __nv_bfloat162 h01, h23, l01, l23;
    h01.x = __float2bfloat16(X.x); h01.y = __float2bfloat16(X.y);
    h23.x = __float2bfloat16(X.z); h23.y = __float2bfloat16(X.w);
    l01.x = __float2bfloat16(X.x - __bfloat162float(h01.x));
    l01.y = __float2bfloat16(X.y - __bfloat162float(h01.y));
    l23.x = __float2bfloat16(X.z - __bfloat162float(h23.x));
    l23.y = __float2bfloat16(X.w - __bfloat162float(h23.y));
    ((__nv_bfloat162*)g_Xhi)[2*i]   = h01;
    ((__nv_bfloat162*)g_Xhi)[2*i+1] = h23;
    ((__nv_bfloat162*)g_Xlo)[2*i]   = l01;
    ((__nv_bfloat162*)g_Xlo)[2*i+1] = l23;
}

// ================= mma.sync bf16 GEMM with hi/lo split =================
// C[M,N] = A[M,K] @ Bt[N,K]^T, 3 products: Ahi*Bhi + Ahi*Blo + Alo*Bhi.
// Block tile 128x128, K-chunk 64 bf16 (128B SW128 rows). 8 warps (2m x 4n), warp 64x32.
// mode 0: C = tanh(v + bias) -> split into g_Hhi/g_Hlo.
// mode 1: partial v -> g_p2[blockIdx.z].
#define TILE_BYTES (128 * 128)   // 128 rows x 64 bf16
#define GEMM_SMEM  (4 * TILE_BYTES)  // Ahi, Alo, Bhi, Blo

__global__ void __launch_bounds__(256, 1) gemm_mma_kernel(
    const __nv_bfloat16* __restrict__ Ahi, const __nv_bfloat16* __restrict__ Alo, int lda,
    const __nv_bfloat16* __restrict__ Bhi, const __nv_bfloat16* __restrict__ Blo, int ldb,
    int nch, int mode, const float* __restrict__ bias)
{
    if (g_ctl.done) return;
    extern __shared__ char smem[];
    char* smAh = smem;
    char* smAl = smem + TILE_BYTES;
    char* smBh = smem + 2 * TILE_BYTES;
    char* smBl = smem + 3 * TILE_BYTES;
    const uint32_t sAh = smem_u32(smAh), sAl = smem_u32(smAl);
    const uint32_t sBh = smem_u32(smBh), sBl = smem_u32(smBl);

    const int tid = threadIdx.x;
    const int w = tid >> 5, l = tid & 31;
    const int wm = w >> 2, wn = w & 3;     // warp tile: rows wm*64, cols wn*32
    const int m0 = blockIdx.y * 128;
    const int n0 = blockIdx.x * 128;
    const int kbase = blockIdx.z * nch * 64;

    float acc[4][4][4];
#pragma unroll
    for (int mf = 0; mf < 4; mf++)
#pragma unroll
        for (int nf = 0; nf < 4; nf++)
#pragma unroll
            for (int e = 0; e < 4; e++) acc[mf][nf][e] = 0.f;

    // ldmatrix lane address components
    const int rowA = wm * 64 + (l & 15);
    const int colA = (l >> 4) * 8;          // 0 or 8
    const int rowB = wn * 32 + (l & 7);
    const int colB = ((l >> 3) & 1) * 8;    // 0 or 8 (lanes 16-31 unused by x2 but valid)

    for (int c = 0; c < nch; c++) {
        const int kc = kbase + c * 64;
        // load A tile 128x64 (hi+lo)
#pragma unroll
        for (int i = 0; i < 4; i++) {
            int t = tid + i * 256;
            int r = t >> 3, g = t & 7;
            size_t src = (size_t)(m0 + r) * lda + kc + g * 8;
            uint32_t sw = SWZ128(r * 128 + g * 16);
            *(uint4*)(smAh + sw) = *(const uint4*)(Ahi + src);
            *(uint4*)(smAl + sw) = *(const uint4*)(Alo + src);
        }
        // load B tile 128x64 (hi+lo), Bt is [N,K] row-major
#pragma unroll
        for (int i = 0; i < 4; i++) {
            int t = tid + i * 256;
            int r = t >> 3, g = t & 7;
            size_t src = (size_t)(n0 + r) * ldb + kc + g * 8;
            uint32_t sw = SWZ128(r * 128 + g * 16);
            *(uint4*)(smBh + sw) = *(const uint4*)(Bhi + src);
            *(uint4*)(smBl + sw) = *(const uint4*)(Blo + src);
        }
        __syncthreads();

#pragma unroll
        for (int kf = 0; kf < 4; kf++) {
            uint32_t ah[4][4], al[4][4], bh[4][2], bl[4][2];
#pragma unroll
            for (int mf = 0; mf < 4; mf++) {
                uint32_t off = SWZ128((rowA + mf * 16) * 128 + (kf * 16 + colA) * 2);
                ldsm_x4(ah[mf], sAh + off);
                ldsm_x4(al[mf], sAl + off);
            }
#pragma unroll
            for (int nf = 0; nf < 4; nf++) {
                uint32_t off = SWZ128((rowB + nf * 8) * 128 + (kf * 16 + colB) * 2);
                ldsm_x2(bh[nf], sBh + off);
                ldsm_x2(bl[nf], sBl + off);
            }
#pragma unroll
            for (int mf = 0; mf < 4; mf++)
#pragma unroll
                for (int nf = 0; nf < 4; nf++) {
                    mma16816(acc[mf][nf], ah[mf], bh[nf]);
                    mma16816(acc[mf][nf], ah[mf], bl[nf]);
                    mma16816(acc[mf][nf], al[mf], bh[nf]);
                }
        }
        __syncthreads();
    }

    // epilogue
    const int rr = l >> 2;
    const int cc2 = (l & 3) * 2;
#pragma unroll
    for (int mf = 0; mf < 4; mf++) {
#pragma unroll
        for (int nf = 0; nf < 4; nf++) {
            int r0 = m0 + wm * 64 + mf * 16 + rr;
            int ci = n0 + wn * 32 + nf * 8 + cc2;
            if (mode == 0) {
                float2 bb = *(const float2*)&bias[ci];
                float v0 = tanhf(acc[mf][nf][0] + bb.x);
                float v1 = tanhf(acc[mf][nf][1] + bb.y);
                float v2 = tanhf(acc[mf][nf][2] + bb.x);
                float v3 = tanhf(acc[mf][nf][3] + bb.y);
                __nv_bfloat162 h, lo2;
                h.x = __float2bfloat16(v0); h.y = __float2bfloat16(v1);
                lo2.x = __float2bfloat16(v0 - __bfloat162float(h.x));
                lo2.y = __float2bfloat16(v1 - __bfloat162float(h.y));
                *(__nv_bfloat162*)&g_Hhi[(size_t)r0 * H_ + ci] = h;
                *(__nv_bfloat162*)&g_Hlo[(size_t)r0 * H_ + ci] = lo2;
                h.x = __float2bfloat16(v2); h.y = __float2bfloat16(v3);
                lo2.x = __float2bfloat16(v2 - __bfloat162float(h.x));
                lo2.y = __float2bfloat16(v3 - __bfloat162float(h.y));
                *(__nv_bfloat162*)&g_Hhi[(size_t)(r0 + 8) * H_ + ci] = h;
                *(__nv_bfloat162*)&g_Hlo[(size_t)(r0 + 8) * H_ + ci] = lo2;
            } else {
                float* part = g_p2 + (size_t)blockIdx.z * ND;
                *(float2*)&part[(size_t)r0 * D_ + ci] = make_float2(acc[mf][nf][0], acc[mf][nf][1]);
                *(float2*)&part[(size_t)(r0 + 8) * D_ + ci] = make_float2(acc[mf][nf][2], acc[mf][nf][3]);
            }
        }
    }
}

// split-K reduce + bias (+ fused dopri5 error partials for stage 6)
__global__ void reduce_kernel(float* __restrict__ kout, const float* __restrict__ b2, int do_err)
{
    if (g_ctl.done) return;
    int i = blockIdx.x * 256 + threadIdx.x;   // float4 index over ND/4
    const float4* p = (const float4*)g_p2;
    float4 v = p[i];
    float4 a = p[NV + i];
    float4 bb = ((const float4*)b2)[i & 63];
    v.x += a.x + bb.x;
    v.y += a.y + bb.y;
    v.z += a.z + bb.z;
    v.w += a.w + bb.w;
    ((float4*)kout)[i] = v;

    if (do_err) {
        const float dt = g_ctl.dt;
        float4 yv  = ((const float4*)g_y)[i];
        float4 y14 = ((const float4*)g_y1)[i];
        float4 k0v = ((const float4*)g_k[0])[i];
        float4 k2v = ((const float4*)g_k[2])[i];
        float4 k3v = ((const float4*)g_k[3])[i];
        float4 k4v = ((const float4*)g_k[4])[i];
        float4 k5v = ((const float4*)g_k[5])[i];
        float s = 0.f;
#define ERRC(cc) { \
        float e = dt * (CE0*k0v.cc + CE2*k2v.cc + CE3*k3v.cc + CE4*k4v.cc + CE5*k5v.cc + CE6*v.cc); \
        float tol = ATOL + RTOL * fmaxf(fabsf(yv.cc), fabsf(y14.cc)); \
        float r = e / tol; s += r * r; }
        ERRC(x) ERRC(y) ERRC(z) ERRC(w)
#undef ERRC
        __shared__ float sm[256];
        sm[threadIdx.x] = s;
        __syncthreads();
        for (int off = 128; off > 0; off >>= 1) {
            if (threadIdx.x < off) sm[threadIdx.x] += sm[threadIdx.x + off];
            __syncthreads();
        }
        if (threadIdx.x == 0) g_part[blockIdx.x] = sm[0];
    }
}

// ---------------- init-step-size reductions ----------------
__global__ void red_d01_kernel() {
    int i = blockIdx.x * 256 + threadIdx.x;
    float4 yv = ((const float4*)g_y)[i];
    float4 fv = ((const float4*)g_k[0])[i];
    float s0 = 0.f, s1 = 0.f;
    {
        float sc, a, b;
        sc = ATOL + fabsf(yv.x) * RTOL; a = yv.x / sc; b = fv.x / sc; s0 += a*a; s1 += b*b;
        sc = ATOL + fabsf(yv.y) * RTOL; a = yv.y / sc; b = fv.y / sc; s0 += a*a; s1 += b*b;
        sc = ATOL + fabsf(yv.z) * RTOL; a = yv.z / sc; b = fv.z / sc; s0 += a*a; s1 += b*b;
        sc = ATOL + fabsf(yv.w) * RTOL; a = yv.w / sc; b = fv.w / sc; s0 += a*a; s1 += b*b;
    }
    __shared__ float sm0[256], sm1[256];
    sm0[threadIdx.x] = s0; sm1[threadIdx.x] = s1;
    __syncthreads();
    for (int off = 128; off > 0; off >>= 1) {
        if (threadIdx.x < off) {
            sm0[threadIdx.x] += sm0[threadIdx.x + off];
            sm1[threadIdx.x] += sm1[threadIdx.x + off];
        }
        __syncthreads();
    }
    if (threadIdx.x == 0) { g_part[blockIdx.x] = sm0[0]; g_part[1024 + blockIdx.x] = sm1[0]; }
}

__global__ void fin_d01_kernel() {
    __shared__ float sm0[256], sm1[256];
    float s0 = 0.f, s1 = 0.f;
    for (int j = threadIdx.x; j < 1024; j += 256) { s0 += g_part[j]; s1 += g_part[1024 + j]; }
    sm0[threadIdx.x] = s0; sm1[threadIdx.x] = s1;
    __syncthreads();
    for (int off = 128; off > 0; off >>= 1) {
        if (threadIdx.x < off) {
            sm0[threadIdx.x] += sm0[threadIdx.x + off];
            sm1[threadIdx.x] += sm1[threadIdx.x + off];
        }
        __syncthreads();
    }
    if (threadIdx.x == 0) {
        float d0 = sqrtf(sm0[0]);
        float d1 = sqrtf(sm1[0]);
        float h0 = (d0 < 1e-5f || d1 < 1e-5f) ? 1e-6f : 0.01f * d0 / d1;
        g_ctl.h0 = h0;
        g_ctl.d1 = d1;
    }
}

__global__ void red_d2_kernel() {
    int i = blockIdx.x * 256 + threadIdx.x;
    float4 yv = ((const float4*)g_y)[i];
    float4 f0 = ((const float4*)g_k[0])[i];
    float4 f1 = ((const float4*)g_k[1])[i];
    float s = 0.f;
    {
        float sc, a;
        sc = ATOL + fabsf(yv.x) * RTOL; a = (f1.x - f0.x) / sc; s += a*a;
        sc = ATOL + fabsf(yv.y) * RTOL; a = (f1.y - f0.y) / sc; s += a*a;
        sc = ATOL + fabsf(yv.z) * RTOL; a = (f1.z - f0.z) / sc; s += a*a;
        sc = ATOL + fabsf(yv.w) * RTOL; a = (f1.w - f0.w) / sc; s += a*a;
    }
    __shared__ float sm[256];
    sm[threadIdx.x] = s;
    __syncthreads();
    for (int off = 128; off > 0; off >>= 1) {
        if (threadIdx.x < off) sm[threadIdx.x] += sm[threadIdx.x + off];
        __syncthreads();
    }
    if (threadIdx.x == 0) g_part[blockIdx.x] = sm[0];
}

__global__ void fin_d2_kernel() {
    __shared__ float sm[256];
    float s = 0.f;
    for (int j = threadIdx.x; j < 1024; j += 256) s += g_part[j];
    sm[threadIdx.x] = s;
    __syncthreads();
    for (int off = 128; off > 0; off >>= 1) {
        if (threadIdx.x < off) sm[threadIdx.x] += sm[threadIdx.x + off];
        __syncthreads();
    }
    if (threadIdx.x == 0) {
        float d2 = sqrtf(sm[0]) / g_ctl.h0;
        float d1 = g_ctl.d1;
        float h1;
        if (d1 <= 1e-15f && d2 <= 1e-15f)
            h1 = fmaxf(1e-6f, g_ctl.h0 * 1e-3f);
        else
            h1 = powf(0.01f / fmaxf(d1, d2), 0.2f);
        float dt = fminf(100.f * g_ctl.h0, h1);
        g_ctl.dt = dt;
        g_ctl.t = 0.f; g_ctl.last_t = 0.f;
        g_ctl.done = 0; g_ctl.accept = 0;
    }
}

// ---------------- controller ----------------
__global__ void ctl_step_kernel() {
    if (g_ctl.done) { if (threadIdx.x == 0) g_ctl.accept = 0; return; }
    __shared__ float sm[256];
    float s = 0.f;
    for (int j = threadIdx.x; j < 1024; j += 256) s += g_part[j];
    sm[threadIdx.x] = s;
    __syncthreads();
    for (int off = 128; off > 0; off >>= 1) {
        if (threadIdx.x < off) sm[threadIdx.x] += sm[threadIdx.x + off];
        __syncthreads();
    }
    if (threadIdx.x == 0) {
        float ratio = sqrtf(sm[0] / (float)ND);
        float t = g_ctl.t, dt = g_ctl.dt;
        float next_t = t + dt;
        int acc = (ratio <= 1.0f);
        float fac;
        if (ratio == 0.f) {
            fac = 10.f;
        } else {
            float r = fmaxf(ratio, 0.f);
            float dfac = (r < 1.f) ? 1.f : 0.2f;
            fac = fminf(10.f, fmaxf(0.9f * powf(r, -0.2f), dfac));
        }
        float ndt = fmaxf(dt * fac, 0.f);
        g_ctl.dt_used = dt;
        g_ctl.dt = ndt;
        g_ctl.accept = acc;
        if (acc) {
            g_ctl.last_t = t;
            g_ctl.t = next_t;
            if (next_t >= 1.0f) g_ctl.done = 1;
        }
    }
}

// ---------------- accept: snapshot, commit, FSAL ----------------
__global__ void apply_kernel() {
    if (!g_ctl.accept) return;
    int i = blockIdx.x * 256 + threadIdx.x;
    float dts = g_ctl.dt_used;
    float4 yv = ((const float4*)g_y)[i];
    float4 y1 = ((const float4*)g_y1)[i];
    float4 k0 = ((const float4*)g_k[0])[i];
    float4 k2 = ((const float4*)g_k[2])[i];
    float4 k3 = ((const float4*)g_k[3])[i];
    float4 k4 = ((const float4*)g_k[4])[i];
    float4 k5 = ((const float4*)g_k[5])[i];
    float4 k6 = ((const float4*)g_k[6])[i];
    float4 ym;
    ym.x = yv.x + dts * (CM0*k0.x + CM2*k2.x + CM3*k3.x + CM4*k4.x + CM5*k5.x + CM6*k6.x);
    ym.y = yv.y + dts * (CM0*k0.y + CM2*k2.y + CM3*k3.y + CM4*k4.y + CM5*k5.y + CM6*k6.y);
    ym.z = yv.z + dts * (CM0*k0.z + CM2*k2.z + CM3*k3.z + CM4*k4.z + CM5*k5.z + CM6*k6.z);
    ym.w = yv.w + dts * (CM0*k0.w + CM2*k2.w + CM3*k3.w + CM4*k4.w + CM5*k5.w + CM6*k6.w);
    ((float4*)g_y0s)[i] = yv;
    ((float4*)g_f0s)[i] = k0;
    ((float4*)g_f1s)[i] = k6;
    ((float4*)g_ymid)[i] = ym;
    ((float4*)g_y)[i] = y1;
    ((float4*)g_k[0])[i] = k6;
}

// ---------------- final quartic interpolation at t=1 ----------------
__global__ void interp_kernel() {
    int i = blockIdx.x * 256 + threadIdx.x;
    float t1 = g_ctl.t, t0 = g_ctl.last_t, dts = g_ctl.dt_used;
    float x = (1.0f - t0) / (t1 - t0);
    float4 y0 = ((const float4*)g_y0s)[i];
    float4 y1 = ((const float4*)g_y)[i];
    float4 f0 = ((const float4*)g_f0s)[i];
    float4 f1 = ((const float4*)g_f1s)[i];
    float4 ym = ((const float4*)g_ymid)[i];
    float4 o;
#define INTERPC(c) { \
        float a = 2.f*dts*(f1.c - f0.c) - 8.f*(y1.c + y0.c) + 16.f*ym.c; \
        float b = dts*(5.f*f0.c - 3.f*f1.c) + 18.f*y0.c + 14.f*y1.c - 32.f*ym.c; \
        float cc = dts*(f1.c - 4.f*f0.c) - 11.f*y0.c - 5.f*y1.c + 16.f*ym.c; \
        float d = dts*f0.c; \
        float e = y0.c; \
        o.c = (((a*x + b)*x + cc)*x + d)*x + e; }
    INTERPC(x) INTERPC(y) INTERPC(z) INTERPC(w)
#undef INTERPC
    ((float4*)g_yout)[i] = o;
}

__global__ void gather_kernel(const int* __restrict__ indices, float* __restrict__ out) {
    int i = blockIdx.x * 256 + threadIdx.x;
    if (i < B_ * K_) {
        int b = i / K_;
        out[i] = g_yout[(size_t)b * D_ + indices[i]];
    }
}

// ---------------- orchestration ----------------
extern "C" void kernel_launch(void* const* d_in, const int* in_sizes, int n_in,
                              void* d_out, int out_size)
{
    const float* x  = (const float*)d_in[0];
    const float* W1 = (const float*)d_in[1];
    const float* b1 = (const float*)d_in[2];
    const float* W2 = (const float*)d_in[3];
    const float* b2 = (const float*)d_in[4];
    const int*  idx = (const int*)d_in[5];
    float* out = (float*)d_out;

    cudaFuncSetAttribute(gemm_mma_kernel, cudaFuncAttributeMaxDynamicSharedMemorySize, GEMM_SMEM);

    float *y, *k[7];
    Ctl* ctl;
    __nv_bfloat16 *Xhi, *Xlo, *Hhi, *Hlo, *W1thi, *W1tlo, *W2thi, *W2tlo;
    cudaGetSymbolAddress((void**)&y,   g_y);
    cudaGetSymbolAddress((void**)&ctl, g_ctl);
    cudaGetSymbolAddress((void**)&Xhi, g_Xhi);
    cudaGetSymbolAddress((void**)&Xlo, g_Xlo);
    cudaGetSymbolAddress((void**)&Hhi, g_Hhi);
    cudaGetSymbolAddress((void**)&Hlo, g_Hlo);
    cudaGetSymbolAddress((void**)&W1thi, g_W1thi);
    cudaGetSymbolAddress((void**)&W1tlo, g_W1tlo);
    cudaGetSymbolAddress((void**)&W2thi, g_W2thi);
    cudaGetSymbolAddress((void**)&W2tlo, g_W2tlo);
    {
        float* kbase;
        cudaGetSymbolAddress((void**)&kbase, g_k);
        for (int j = 0; j < 7; j++) k[j] = kbase + (size_t)j * ND;
    }
    const float* dt_ptr = &ctl->dt;
    const float* h0_ptr = &ctl->h0;

    dim3 gg1(8, 32, 1);   // GEMM1: N=1024/128, M=4096/128
    dim3 gg2(2, 32, 2);   // GEMM2: N=256/128, split-K 2
    dim3 blk(256);
    dim3 ge(NV / 256), be(256);

    auto feval = [&](float* kout, int do_err) {
        gemm_mma_kernel<<<gg1, blk, GEMM_SMEM>>>(Xhi, Xlo, D_, W1thi, W1tlo, D_, 4, 0, b1);
        gemm_mma_kernel<<<gg2, blk, GEMM_SMEM>>>(Hhi, Hlo, H_, W2thi, W2tlo, H_, 8, 1, nullptr);
        reduce_kernel<<<ge, be>>>(kout, b2, do_err);
    };

    // dopri5 Butcher tableau
    const float B21 = (float)(1.0/5.0);
    const float B31 = (float)(3.0/40.0),   B32 = (float)(9.0/40.0);
    const float B41 = (float)(44.0/45.0),  B42 = (float)(-56.0/15.0),  B43 = (float)(32.0/9.0);
    const float B51 = (float)(19372.0/6561.0), B52 = (float)(-25360.0/2187.0),
                B53 = (float)(64448.0/6561.0), B54 = (float)(-212.0/729.0);
    const float B61 = (float)(9017.0/3168.0),  B62 = (float)(-355.0/33.0),
                B63 = (float)(46732.0/5247.0), B64 = (float)(49.0/176.0),
                B65 = (float)(-5103.0/18656.0);
    const float CS0 = (float)(35.0/384.0), CS2 = (float)(500.0/1113.0),
                CS3 = (float)(125.0/192.0), CS4 = (float)(-2187.0/6784.0),
                CS5 = (float)(11.0/84.0);

    // init
    ctl_init_kernel<<<1, 32>>>();
    copy_kernel<<<ge, be>>>((const float4*)x, (float4*)y);
    prep_w1_kernel<<<1024, 256>>>(W1);
    prep_w2_kernel<<<1024, 256>>>(W2);
    // k0 = f(y)
    split_combine_kernel<<<ge, be>>>((const float4*)y, h0_ptr, 0,
                                     0.f, 0.f, 0.f, 0.f, 0.f, 0.f, 0);
    feval(k[0], 0);
    // initial step size (Hairer)
    red_d01_kernel<<<ge, be>>>();
    fin_d01_kernel<<<1, 256>>>();
    split_combine_kernel<<<ge, be>>>((const float4*)y, h0_ptr, 1,
                                     1.f, 0.f, 0.f, 0.f, 0.f, 0.f, 0);
    feval(k[1], 0);
    red_d2_kernel<<<ge, be>>>();
    fin_d2_kernel<<<1, 256>>>();

    for (int s = 0; s < NMAX; s++) {
        split_combine_kernel<<<ge, be>>>((const float4*)y, dt_ptr, 1,
                                         B21, 0.f, 0.f, 0.f, 0.f, 0.f, 0);
        feval(k[1], 0);
        split_combine_kernel<<<ge, be>>>((const float4*)y, dt_ptr, 2,
                                         B31, B32, 0.f, 0.f, 0.f, 0.f, 0);
        feval(k[2], 0);
        split_combine_kernel<<<ge, be>>>((const float4*)y, dt_ptr, 3,
                                         B41, B42, B43, 0.f, 0.f, 0.f, 0);
        feval(k[3], 0);
        split_combine_kernel<<<ge, be>>>((const float4*)y, dt_ptr, 4,
                                         B51, B52, B53, B54, 0.f, 0.f, 0);
        feval(k[4], 0);
        split_combine_kernel<<<ge, be>>>((const float4*)y, dt_ptr, 5,
                                         B61, B62, B63, B64, B65, 0.f, 0);
        feval(k[5], 0);
        // stage 6: candidate y1 (fp32) + k6 = f(y1), fused err partials
        split_combine_kernel<<<ge, be>>>((const float4*)y, dt_ptr, 6,
                                         CS0, 0.f, CS2, CS3, CS4, CS5, 1);
        feval(k[6], 1);
        ctl_step_kernel<<<1, 256>>>();
        apply_kernel<<<ge, be>>>();
    }

    interp_kernel<<<ge, be>>>();
    {
        int n = B_ * K_;
        gather_kernel<<<(n + 255) / 256, 256>>>(idx, out);
    }
}